// round 9
// baseline (speedup 1.0000x reference)
#include <cuda_runtime.h>
#include <cuda_fp16.h>
#include <math.h>
#include <math_constants.h>
#include <cstdint>

// ---------------- problem constants ----------------
#define DIMV   2048
#define SEQ    2048
#define BATCH  4
#define NHEAD  16
#define NKV    4
#define HD     128
#define HALF   64
#define QKVW   (DIMV + 2 * NKV * HD)   // 3072
#define NTOK   (BATCH * SEQ)           // 8192
#define RMS_EPS 1.1920929e-07f
#define ATT_SCALE 0.08838834764831845f // 1/sqrt(128)

// ---------------- scratch ----------------
__device__ __half g_qkvh[(size_t)NTOK * QKVW];   // 48 MB
__device__ __half g_yh[(size_t)NTOK * DIMV];     // 32 MB
__device__ __half g_xh[(size_t)NTOK * DIMV];     // 32 MB
__device__ __half g_wqh[(size_t)QKVW * DIMV];    // 12 MB (W_qkv^T, [N][K])
__device__ __half g_woh[(size_t)DIMV * DIMV];    //  8 MB (W_out^T, [N][K])
__device__ float  g_cos[SEQ * HALF];
__device__ float  g_sin[SEQ * HALF];

// ---------------- helpers ----------------
__device__ __forceinline__ void cp_async16(void* dst_smem, const void* src_gmem) {
    unsigned d = (unsigned)__cvta_generic_to_shared(dst_smem);
    asm volatile("cp.async.cg.shared.global [%0], [%1], 16;\n" :: "r"(d), "l"(src_gmem));
}
#define CP_COMMIT asm volatile("cp.async.commit_group;\n" ::: "memory")
#define CP_WAIT0  asm volatile("cp.async.wait_group 0;\n" ::: "memory")
#define CP_WAIT1  asm volatile("cp.async.wait_group 1;\n" ::: "memory")

__device__ __forceinline__ uint32_t smem_u32(const void* p) {
    uint32_t a;
    asm("{ .reg .u64 t; cvta.to.shared.u64 t, %1; cvt.u32.u64 %0, t; }" : "=r"(a) : "l"(p));
    return a;
}
__device__ __forceinline__ void ldsm_x4(uint32_t addr, unsigned* r) {
    asm volatile("ldmatrix.sync.aligned.m8n8.x4.shared.b16 {%0,%1,%2,%3}, [%4];"
                 : "=r"(r[0]), "=r"(r[1]), "=r"(r[2]), "=r"(r[3]) : "r"(addr));
}
__device__ __forceinline__ void ldsm_x4_t(uint32_t addr, unsigned* r) {
    asm volatile("ldmatrix.sync.aligned.m8n8.x4.trans.shared.b16 {%0,%1,%2,%3}, [%4];"
                 : "=r"(r[0]), "=r"(r[1]), "=r"(r[2]), "=r"(r[3]) : "r"(addr));
}
__device__ __forceinline__ void mma_f16(float* c, const unsigned* a, const unsigned* b) {
    asm volatile(
        "mma.sync.aligned.m16n8k16.row.col.f32.f16.f16.f32 "
        "{%0,%1,%2,%3}, {%4,%5,%6,%7}, {%8,%9}, {%0,%1,%2,%3};\n"
        : "+f"(c[0]), "+f"(c[1]), "+f"(c[2]), "+f"(c[3])
        : "r"(a[0]), "r"(a[1]), "r"(a[2]), "r"(a[3]), "r"(b[0]), "r"(b[1]));
}
__device__ __forceinline__ unsigned packh2(float lo, float hi) {
    __half2 h = __halves2half2(__float2half_rn(lo), __float2half_rn(hi));
    return *(unsigned*)&h;
}

// ======================================================================
// Merged prep: RoPE tables | x->half | Wqkv transpose+half | Wout transpose+half
// ======================================================================
#define PREP_ROPE   512
#define PREP_X      16384
#define PREP_WQ     (96 * 64)
#define PREP_WO     (64 * 64)
#define PREP_BLOCKS (PREP_ROPE + PREP_X + PREP_WQ + PREP_WO)

__global__ __launch_bounds__(256) void prep_kernel(
    const float* __restrict__ x, const float* __restrict__ Wqkv, const float* __restrict__ Wout,
    __half* __restrict__ xh, __half* __restrict__ wqh, __half* __restrict__ woh,
    float* __restrict__ ct, float* __restrict__ st)
{
    __shared__ float t[32][33];
    const int bx = blockIdx.x;
    const int tid = threadIdx.x;

    if (bx < PREP_ROPE) {
        int idx = bx * 256 + tid;
        int s = idx >> 6;
        int f = idx & 63;
        double inv = pow(10000.0, -((double)(2 * f)) / 128.0);
        double th = (double)s * inv;
        ct[idx] = (float)cos(th);
        st[idx] = (float)sin(th);
        return;
    }
    if (bx < PREP_ROPE + PREP_X) {
        size_t i = (size_t)(bx - PREP_ROPE) * 256 + tid;
        float4 v = ((const float4*)x)[i];
        ((__half2*)xh)[2 * i]     = __halves2half2(__float2half_rn(v.x), __float2half_rn(v.y));
        ((__half2*)xh)[2 * i + 1] = __halves2half2(__float2half_rn(v.z), __float2half_rn(v.w));
        return;
    }
    const float* src;
    __half* dst;
    int R, C, b;
    if (bx < PREP_ROPE + PREP_X + PREP_WQ) {
        b = bx - (PREP_ROPE + PREP_X);
        src = Wqkv; dst = wqh; R = DIMV; C = QKVW;
        int cb = b % 96, rb = b / 96;
        int c0 = cb * 32, r0 = rb * 32;
        int tx = tid & 31, ty = tid >> 5;
#pragma unroll
        for (int j = 0; j < 4; j++)
            t[ty + j * 8][tx] = src[(size_t)(r0 + ty + j * 8) * C + c0 + tx];
        __syncthreads();
#pragma unroll
        for (int j = 0; j < 4; j++)
            dst[(size_t)(c0 + ty + j * 8) * R + r0 + tx] = __float2half_rn(t[tx][ty + j * 8]);
        return;
    }
    b = bx - (PREP_ROPE + PREP_X + PREP_WQ);
    src = Wout; dst = woh; R = DIMV; C = DIMV;
    {
        int cb = b % 64, rb = b / 64;
        int c0 = cb * 32, r0 = rb * 32;
        int tx = tid & 31, ty = tid >> 5;
#pragma unroll
        for (int j = 0; j < 4; j++)
            t[ty + j * 8][tx] = src[(size_t)(r0 + ty + j * 8) * C + c0 + tx];
        __syncthreads();
#pragma unroll
        for (int j = 0; j < 4; j++)
            dst[(size_t)(c0 + ty + j * 8) * R + r0 + tx] = __float2half_rn(t[tx][ty + j * 8]);
    }
}

// ---------------- GEMM geometry: CTA 128x128, 4 warps, warp tile 64x64, BK=64 ----------------
#define GBM 128
#define GBN 128
#define GBK 64
#define GA_BYTES (GBM * GBK * 2)           // 16384
#define GB_BYTES (GBN * GBK * 2)           // 16384
#define GSTAGE_BYTES (GA_BYTES + GB_BYTES) // 32768
#define GSMEM_BYTES (3 * GSTAGE_BYTES)     // 98304

// 128 threads; warp: wm = warp>>1 (row band of 64), wn = warp&1 (col band of 64)
#define GEMM_MAINLOOP(Aptr, Bptr, Kdim)                                            \
    auto issue_load = [&](int bufi, int k0) {                                      \
        char* s = smc + bufi * GSTAGE_BYTES;                                       \
        _Pragma("unroll")                                                          \
        for (int rep = 0; rep < 8; rep++) {                                        \
            int idx = tid + rep * 128;                                             \
            int m = idx >> 3, c16 = idx & 7;                                       \
            cp_async16(s + m * 128 + ((c16 ^ (m & 7)) << 4),                       \
                       (Aptr) + (size_t)(row0 + m) * (Kdim) + k0 + c16 * 8);       \
        }                                                                          \
        char* sb = s + GA_BYTES;                                                   \
        _Pragma("unroll")                                                          \
        for (int rep = 0; rep < 8; rep++) {                                        \
            int idx = tid + rep * 128;                                             \
            int n = idx >> 3, c16 = idx & 7;                                       \
            cp_async16(sb + n * 128 + ((c16 ^ (n & 7)) << 4),                      \
                       (Bptr) + (size_t)(col0 + n) * (Kdim) + k0 + c16 * 8);       \
        }                                                                          \
    };                                                                             \
    const int NIT = (Kdim) / GBK;                                                  \
    const int arow_off = ((lane >> 3) & 1) * 8 + (lane & 7);                       \
    const int aseg_hi  = lane >> 4;                                                \
    const int brow_off = ((lane >> 4) & 1) * 8 + (lane & 7);                       \
    const int bseg_hi  = (lane >> 3) & 1;                                          \
    issue_load(0, 0); CP_COMMIT;                                                   \
    issue_load(1, GBK); CP_COMMIT;                                                 \
    int buf = 0, nbuf = 2;                                                         \
    for (int it = 0; it < NIT; it++) {                                             \
        CP_WAIT1;                                                                  \
        __syncthreads();                                                           \
        if (it + 2 < NIT) issue_load(nbuf, (it + 2) * GBK);                        \
        CP_COMMIT;                                                                 \
        const uint32_t sA = sbase + buf * GSTAGE_BYTES;                            \
        const uint32_t sB = sA + GA_BYTES;                                         \
        _Pragma("unroll")                                                          \
        for (int ks = 0; ks < 4; ks++) {                                           \
            unsigned af[4][4], bfr[4][4];                                          \
            _Pragma("unroll")                                                      \
            for (int mt = 0; mt < 4; mt++) {                                       \
                int rrow = wm * 64 + mt * 16 + arow_off;                           \
                int seg = ks * 2 + aseg_hi;                                        \
                ldsm_x4(sA + rrow * 128 + ((seg ^ (rrow & 7)) << 4), af[mt]);      \
            }                                                                      \
            _Pragma("unroll")                                                      \
            for (int p = 0; p < 4; p++) {                                          \
                int rrow = wn * 64 + p * 16 + brow_off;                            \
                int seg = ks * 2 + bseg_hi;                                        \
                ldsm_x4(sB + rrow * 128 + ((seg ^ (rrow & 7)) << 4), bfr[p]);      \
            }                                                                      \
            _Pragma("unroll")                                                      \
            for (int mt = 0; mt < 4; mt++)                                         \
                _Pragma("unroll")                                                  \
                for (int nt = 0; nt < 8; nt++)                                     \
                    mma_f16(acc[mt][nt], af[mt],                                   \
                            (nt & 1) ? &bfr[nt >> 1][2] : &bfr[nt >> 1][0]);       \
        }                                                                          \
        __syncthreads();                                                           \
        buf = (buf == 2) ? 0 : buf + 1;                                            \
        nbuf = (nbuf == 2) ? 0 : nbuf + 1;                                         \
    }

// ======================================================================
// GEMM1 fused: qkvh = rmsnorm+rope( x @ Wqkv ) as fp16.
// CTA tile 128x128 = exactly ONE head. blockIdx.x: 0..15 Q, 16..19 K, 20..23 V.
// ======================================================================
#define XS_STRIDE 132
#define PR_OFF (128 * XS_STRIDE * 4)       // 67584; pr float[128][2] after xs

__global__ __launch_bounds__(128, 2) void gemm1_fused_kernel(
    const __half* __restrict__ A, const __half* __restrict__ Bt,
    __half* __restrict__ qkvh,
    const float* __restrict__ ct, const float* __restrict__ st)
{
    extern __shared__ char smc[];
    const uint32_t sbase = smem_u32(smc);
    const int tid = threadIdx.x;
    const int warp = tid >> 5;
    const int lane = tid & 31;
    const int grp = lane >> 2;
    const int tig = lane & 3;
    const int wm = warp >> 1;       // 2 row bands of 64
    const int wn = warp & 1;        // 2 col bands of 64
    const int row0 = blockIdx.y * GBM;
    const int col0 = blockIdx.x * GBN;

    float acc[4][8][4];
#pragma unroll
    for (int mt = 0; mt < 4; mt++)
#pragma unroll
        for (int nt = 0; nt < 8; nt++)
#pragma unroll
            for (int r = 0; r < 4; r++) acc[mt][nt][r] = 0.f;

    GEMM_MAINLOOP(A, Bt, DIMV)

    if (blockIdx.x >= 20) {
        // ---- V heads: plain half convert ----
#pragma unroll
        for (int mt = 0; mt < 4; mt++) {
            int row = row0 + wm * 64 + mt * 16 + grp;
#pragma unroll
            for (int nt = 0; nt < 8; nt++) {
                int col = col0 + wn * 64 + nt * 8 + tig * 2;
                *(unsigned*)(qkvh + (size_t)row * QKVW + col) =
                    packh2(acc[mt][nt][0], acc[mt][nt][1]);
                *(unsigned*)(qkvh + (size_t)(row + 8) * QKVW + col) =
                    packh2(acc[mt][nt][2], acc[mt][nt][3]);
            }
        }
        return;
    }

    // ---- Q/K heads: fused RMS-norm + RoPE over this 128-col head ----
    float* xs = (float*)smc;                 // [128][132]
    float* pr = (float*)(smc + PR_OFF);      // [128][2]

    // per-thread sum of squares (this warp's 64-col band), reduce over tig group
#pragma unroll
    for (int mt = 0; mt < 4; mt++) {
        float s0 = 0.f, s1 = 0.f;
#pragma unroll
        for (int nt = 0; nt < 8; nt++) {
            s0 += acc[mt][nt][0] * acc[mt][nt][0] + acc[mt][nt][1] * acc[mt][nt][1];
            s1 += acc[mt][nt][2] * acc[mt][nt][2] + acc[mt][nt][3] * acc[mt][nt][3];
        }
        s0 += __shfl_xor_sync(0xffffffffu, s0, 1);
        s0 += __shfl_xor_sync(0xffffffffu, s0, 2);
        s1 += __shfl_xor_sync(0xffffffffu, s1, 1);
        s1 += __shfl_xor_sync(0xffffffffu, s1, 2);
        if (tig == 0) {
            pr[(wm * 64 + mt * 16 + grp) * 2 + wn]     = s0;
            pr[(wm * 64 + mt * 16 + grp + 8) * 2 + wn] = s1;
        }
    }
    __syncthreads();

    // normalize into smem staging
#pragma unroll
    for (int mt = 0; mt < 4; mt++) {
        int r0l = wm * 64 + mt * 16 + grp;
        int r1l = r0l + 8;
        float sc0 = rsqrtf((pr[r0l * 2] + pr[r0l * 2 + 1]) * (1.0f / 128.0f) + RMS_EPS);
        float sc1 = rsqrtf((pr[r1l * 2] + pr[r1l * 2 + 1]) * (1.0f / 128.0f) + RMS_EPS);
#pragma unroll
        for (int nt = 0; nt < 8; nt++) {
            int col = wn * 64 + nt * 8 + tig * 2;
            xs[r0l * XS_STRIDE + col]     = acc[mt][nt][0] * sc0;
            xs[r0l * XS_STRIDE + col + 1] = acc[mt][nt][1] * sc0;
            xs[r1l * XS_STRIDE + col]     = acc[mt][nt][2] * sc1;
            xs[r1l * XS_STRIDE + col + 1] = acc[mt][nt][3] * sc1;
        }
    }
    __syncthreads();

    // RoPE: pair (f, f+64); coalesced half2 stores. 4 warps x 32 rows.
    const float2* ctp = (const float2*)ct;
    const float2* stp = (const float2*)st;
#pragma unroll 4
    for (int rr = 0; rr < 32; rr++) {
        int row = warp * 32 + rr;
        int s = (row0 + row) & (SEQ - 1);
        float2 xa = *(const float2*)&xs[row * XS_STRIDE + 2 * lane];
        float2 xb = *(const float2*)&xs[row * XS_STRIDE + 64 + 2 * lane];
        float2 c = ctp[s * 32 + lane];
        float2 sn = stp[s * 32 + lane];
        unsigned lo = packh2(xa.x * c.x + xb.x * sn.x, xa.y * c.y + xb.y * sn.y);
        unsigned hi = packh2(xb.x * c.x - xa.x * sn.x, xb.y * c.y - xa.y * sn.y);
        size_t gb = (size_t)(row0 + row) * QKVW + col0 + 2 * lane;
        *(unsigned*)(qkvh + gb)      = lo;
        *(unsigned*)(qkvh + gb + 64) = hi;
    }
}

// ======================================================================
// GEMM2: out[M,N] fp32 = A[M,K] @ Bt[N,K]^T
// ======================================================================
__global__ __launch_bounds__(128, 2) void gemm_f16_kernel(
    const __half* __restrict__ A, const __half* __restrict__ Bt, float* __restrict__ C,
    int M, int N, int K)
{
    extern __shared__ char smc[];
    const uint32_t sbase = smem_u32(smc);
    const int tid = threadIdx.x;
    const int warp = tid >> 5;
    const int lane = tid & 31;
    const int grp = lane >> 2;
    const int tig = lane & 3;
    const int wm = warp >> 1;
    const int wn = warp & 1;
    const int row0 = blockIdx.y * GBM;
    const int col0 = blockIdx.x * GBN;

    float acc[4][8][4];
#pragma unroll
    for (int mt = 0; mt < 4; mt++)
#pragma unroll
        for (int nt = 0; nt < 8; nt++)
#pragma unroll
            for (int r = 0; r < 4; r++) acc[mt][nt][r] = 0.f;

    GEMM_MAINLOOP(A, Bt, K)

#pragma unroll
    for (int mt = 0; mt < 4; mt++) {
        int row = row0 + wm * 64 + mt * 16 + grp;
#pragma unroll
        for (int nt = 0; nt < 8; nt++) {
            int col = col0 + wn * 64 + nt * 8 + tig * 2;
            *(float2*)(C + (size_t)row * N + col) =
                make_float2(acc[mt][nt][0], acc[mt][nt][1]);
            *(float2*)(C + (size_t)(row + 8) * N + col) =
                make_float2(acc[mt][nt][2], acc[mt][nt][3]);
        }
    }
}

// ======================================================================
// FP16 flash attention (unchanged from R8)
// ======================================================================
#define AT_SMEM_BYTES 65536

__global__ __launch_bounds__(256, 1) void attn_f16_kernel(
    const __half* __restrict__ qkvh, __half* __restrict__ yh)
{
    extern __shared__ char smc[];
    const uint32_t sbase = smem_u32(smc);
    const int tid = threadIdx.x;
    const int warp = tid >> 5;
    const int lane = tid & 31;
    const int grp = lane >> 2;
    const int tig = lane & 3;

    const int i0 = (gridDim.x - 1 - blockIdx.x) * 128;
    const int bh = blockIdx.y;
    const int b = bh >> 4;
    const int h = bh & 15;
    const int kvh = h >> 2;

    const size_t rowb = (size_t)b * SEQ * QKVW;
    const int qcol = h * HD;
    const int kcol = DIMV + kvh * HD;
    const int vcol = DIMV + NKV * HD + kvh * HD;

#pragma unroll
    for (int rep = 0; rep < 8; rep++) {
        int idx = tid + rep * 256;
        int row = idx >> 4, seg = idx & 15;
        cp_async16(smc + row * 256 + ((seg ^ (row & 7)) << 4),
                   qkvh + rowb + (size_t)(i0 + row) * QKVW + qcol + seg * 8);
    }
    CP_COMMIT; CP_WAIT0;
    __syncthreads();

    const int arow_off = ((lane >> 3) & 1) * 8 + (lane & 7);
    const int aseg_hi  = lane >> 4;
    unsigned qf[8][4];
    {
        int row = warp * 16 + arow_off;
#pragma unroll
        for (int ks = 0; ks < 8; ks++) {
            int seg = ks * 2 + aseg_hi;
            ldsm_x4(sbase + row * 256 + ((seg ^ (row & 7)) << 4), qf[ks]);
        }
    }
    __syncthreads();

    auto issue_kv = [&](int buf, int j0) {
        char* Ks = smc + buf * 32768;
        char* Vs = Ks + 16384;
#pragma unroll
        for (int rep = 0; rep < 4; rep++) {
            int idx = tid + rep * 256;
            int row = idx >> 4, seg = idx & 15;
            const __half* kr = qkvh + rowb + (size_t)(j0 + row) * QKVW;
            uint32_t d = row * 256 + ((seg ^ (row & 7)) << 4);
            cp_async16(Ks + d, kr + kcol + seg * 8);
            cp_async16(Vs + d, kr + vcol + seg * 8);
        }
    };

    float of[16][4];
#pragma unroll
    for (int nf = 0; nf < 16; nf++)
#pragma unroll
        for (int r = 0; r < 4; r++) of[nf][r] = 0.f;
    float m0 = -CUDART_INF_F, m1 = -CUDART_INF_F, l0 = 0.f, l1 = 0.f;

    const int qi0 = i0 + warp * 16 + grp;
    const int qi1 = qi0 + 8;
    const int wrow_max = i0 + warp * 16 + 15;
    const int NIT = (i0 + 128) / 64;

    const int brow_off = ((lane >> 4) & 1) * 8 + (lane & 7);
    const int bseg_hi  = (lane >> 3) & 1;
    const int vrow_off = ((lane >> 3) & 1) * 8 + (lane & 7);
    const int vseg_hi  = (lane >> 4) & 1;

    issue_kv(0, 0); CP_COMMIT;

    for (int it = 0; it < NIT; it++) {
        const int j0 = it * 64;
        const int buf = it & 1;
        if (it + 1 < NIT) issue_kv(buf ^ 1, j0 + 64);
        CP_COMMIT;
        CP_WAIT1;
        __syncthreads();

        if (j0 <= wrow_max) {
            const uint32_t Kb = sbase + buf * 32768;
            const uint32_t Vb = Kb + 16384;

            float sacc[8][4];
#pragma unroll
            for (int nf = 0; nf < 8; nf++)
#pragma unroll
                for (int r = 0; r < 4; r++) sacc[nf][r] = 0.f;

#pragma unroll
            for (int ks = 0; ks < 8; ks++) {
                unsigned bf[4][4];
#pragma unroll
                for (int p = 0; p < 4; p++) {
                    int row = p * 16 + brow_off;
                    int seg = ks * 2 + bseg_hi;
                    ldsm_x4(Kb + row * 256 + ((seg ^ (row & 7)) << 4), bf[p]);
                }
#pragma unroll
                for (int nf = 0; nf < 8; nf++)
                    mma_f16(sacc[nf], qf[ks], (nf & 1) ? &bf[nf >> 1][2] : &bf[nf >> 1][0]);
            }

            if (j0 + 63 > i0) {
#pragma unroll
                for (int nf = 0; nf < 8; nf++) {
                    int key = j0 + nf * 8 + 2 * tig;
                    if (key     > qi0) sacc[nf][0] = -CUDART_INF_F;
                    if (key + 1 > qi0) sacc[nf][1] = -CUDART_INF_F;
                    if (key     > qi1) sacc[nf][2] = -CUDART_INF_F;
                    if (key + 1 > qi1) sacc[nf][3] = -CUDART_INF_F;
                }
            }

            float mx0 = -CUDART_INF_F, mx1 = -CUDART_INF_F;
#pragma unroll
            for (int nf = 0; nf < 8; nf++) {
                mx0 = fmaxf(mx0, fmaxf(sacc[nf][0], sacc[nf][1]));
                mx1 = fmaxf(mx1, fmaxf(sacc[nf][2], sacc[nf][3]));
            }
            mx0 = fmaxf(mx0, __shfl_xor_sync(0xffffffffu, mx0, 1));
            mx0 = fmaxf(mx0, __shfl_xor_sync(0xffffffffu, mx0, 2));
            mx1 = fmaxf(mx1, __shfl_xor_sync(0xffffffffu, mx1, 1));
            mx1 = fmaxf(mx1, __shfl_xor_sync(0xffffffffu, mx1, 2));

            float m0n = fmaxf(m0, mx0);
            float m1n = fmaxf(m1, mx1);
            float alpha0 = __expf((m0 - m0n) * ATT_SCALE);
            float alpha1 = __expf((m1 - m1n) * ATT_SCALE);
            m0 = m0n; m1 = m1n;

            unsigned ph[8][2];
            float rs0 = 0.f, rs1 = 0.f;
#pragma unroll
            for (int nf = 0; nf < 8; nf++) {
                float p0 = __expf((sacc[nf][0] - m0) * ATT_SCALE);
                float p1 = __expf((sacc[nf][1] - m0) * ATT_SCALE);
                float p2 = __expf((sacc[nf][2] - m1) * ATT_SCALE);
                float p3 = __expf((sacc[nf][3] - m1) * ATT_SCALE);
                rs0 += p0 + p1;
                rs1 += p2 + p3;
                ph[nf][0] = packh2(p0, p1);
                ph[nf][1] = packh2(p2, p3);
            }
            rs0 += __shfl_xor_sync(0xffffffffu, rs0, 1);
            rs0 += __shfl_xor_sync(0xffffffffu, rs0, 2);
            rs1 += __shfl_xor_sync(0xffffffffu, rs1, 1);
            rs1 += __shfl_xor_sync(0xffffffffu, rs1, 2);
            l0 = l0 * alpha0 + rs0;
            l1 = l1 * alpha1 + rs1;

#pragma unroll
            for (int nf = 0; nf < 16; nf++) {
                of[nf][0] *= alpha0; of[nf][1] *= alpha0;
                of[nf][2] *= alpha1; of[nf][3] *= alpha1;
            }

#pragma unroll
            for (int ks = 0; ks < 4; ks++) {
                unsigned af[4] = {ph[2 * ks][0], ph[2 * ks][1],
                                  ph[2 * ks + 1][0], ph[2 * ks + 1][1]};
#pragma unroll
                for (int p = 0; p < 8; p++) {
                    int row = ks * 16 + vrow_off;
                    int seg = p * 2 + vseg_hi;
                    unsigned vf[4];
                    ldsm_x4_t(Vb + row * 256 + ((seg ^ (row & 7)) << 4), vf);
                    mma_f16(of[2 * p],     af, &vf[0]);
                    mma_f16(of[2 * p + 1], af, &vf[2]);
                }
            }
        }
        __syncthreads();
    }

    float inv0 = 1.0f / l0, inv1 = 1.0f / l1;
    int r0 = i0 + warp * 16 + grp;
    __half* dst0 = yh + (size_t)(b * SEQ + r0) * DIMV + h * HD;
    __half* dst1 = yh + (size_t)(b * SEQ + r0 + 8) * DIMV + h * HD;
#pragma unroll
    for (int nf = 0; nf < 16; nf++) {
        *(unsigned*)(dst0 + nf * 8 + 2 * tig) = packh2(of[nf][0] * inv0, of[nf][1] * inv0);
        *(unsigned*)(dst1 + nf * 8 + 2 * tig) = packh2(of[nf][2] * inv1, of[nf][3] * inv1);
    }
}

// ================= launch =================
extern "C" void kernel_launch(void* const* d_in, const int* in_sizes, int n_in,
                              void* d_out, int out_size)
{
    const float* x    = (const float*)d_in[0];
    const float* Wqkv = (const float*)d_in[1];
    const float* Wout = (const float*)d_in[2];
    float* out = (float*)d_out;

    float *ct, *st;
    __half *qkvh, *yh, *xh, *wqh, *woh;
    cudaGetSymbolAddress((void**)&qkvh, g_qkvh);
    cudaGetSymbolAddress((void**)&yh,   g_yh);
    cudaGetSymbolAddress((void**)&xh,   g_xh);
    cudaGetSymbolAddress((void**)&wqh,  g_wqh);
    cudaGetSymbolAddress((void**)&woh,  g_woh);
    cudaGetSymbolAddress((void**)&ct,   g_cos);
    cudaGetSymbolAddress((void**)&st,   g_sin);

    // 1. merged prep
    prep_kernel<<<PREP_BLOCKS, 256>>>(x, Wqkv, Wout, xh, wqh, woh, ct, st);

    // 2. QKV projection fused with RMS-norm + RoPE -> fp16 qkv
    cudaFuncSetAttribute(gemm1_fused_kernel, cudaFuncAttributeMaxDynamicSharedMemorySize, GSMEM_BYTES);
    gemm1_fused_kernel<<<dim3(QKVW / GBN, NTOK / GBM), 128, GSMEM_BYTES>>>(
        xh, wqh, qkvh, ct, st);

    // 3. causal GQA flash attention
    cudaFuncSetAttribute(attn_f16_kernel, cudaFuncAttributeMaxDynamicSharedMemorySize, AT_SMEM_BYTES);
    attn_f16_kernel<<<dim3(SEQ / 128, BATCH * NHEAD), 256, AT_SMEM_BYTES>>>(qkvh, yh);

    // 4. output projection
    cudaFuncSetAttribute(gemm_f16_kernel, cudaFuncAttributeMaxDynamicSharedMemorySize, GSMEM_BYTES);
    gemm_f16_kernel<<<dim3(DIMV / GBN, NTOK / GBM), 128, GSMEM_BYTES>>>(
        yh, woh, out, NTOK, DIMV, DIMV);
}

// round 10
// speedup vs baseline: 1.0621x; 1.0621x over previous
#include <cuda_runtime.h>
#include <cuda_fp16.h>
#include <math.h>
#include <math_constants.h>
#include <cstdint>

// ---------------- problem constants ----------------
#define DIMV   2048
#define SEQ    2048
#define BATCH  4
#define NHEAD  16
#define NKV    4
#define HD     128
#define HALF   64
#define QKVW   (DIMV + 2 * NKV * HD)   // 3072
#define NTOK   (BATCH * SEQ)           // 8192
#define RMS_EPS 1.1920929e-07f
#define ATT_SCALE 0.08838834764831845f // 1/sqrt(128)

// ---------------- scratch ----------------
__device__ __half g_qkvh[(size_t)NTOK * QKVW];   // 48 MB
__device__ __half g_yh[(size_t)NTOK * DIMV];     // 32 MB
__device__ __half g_xh[(size_t)NTOK * DIMV];     // 32 MB
__device__ __half g_wqh[(size_t)QKVW * DIMV];    // 12 MB (W_qkv^T, [N][K])
__device__ __half g_woh[(size_t)DIMV * DIMV];    //  8 MB (W_out^T, [N][K])
__device__ float  g_cos[SEQ * HALF];
__device__ float  g_sin[SEQ * HALF];

// ---------------- helpers ----------------
__device__ __forceinline__ void cp_async16(void* dst_smem, const void* src_gmem) {
    unsigned d = (unsigned)__cvta_generic_to_shared(dst_smem);
    asm volatile("cp.async.cg.shared.global [%0], [%1], 16;\n" :: "r"(d), "l"(src_gmem));
}
#define CP_COMMIT asm volatile("cp.async.commit_group;\n" ::: "memory")
#define CP_WAIT0  asm volatile("cp.async.wait_group 0;\n" ::: "memory")
#define CP_WAIT1  asm volatile("cp.async.wait_group 1;\n" ::: "memory")

__device__ __forceinline__ uint32_t smem_u32(const void* p) {
    uint32_t a;
    asm("{ .reg .u64 t; cvta.to.shared.u64 t, %1; cvt.u32.u64 %0, t; }" : "=r"(a) : "l"(p));
    return a;
}
__device__ __forceinline__ void ldsm_x4(uint32_t addr, unsigned* r) {
    asm volatile("ldmatrix.sync.aligned.m8n8.x4.shared.b16 {%0,%1,%2,%3}, [%4];"
                 : "=r"(r[0]), "=r"(r[1]), "=r"(r[2]), "=r"(r[3]) : "r"(addr));
}
__device__ __forceinline__ void ldsm_x4_t(uint32_t addr, unsigned* r) {
    asm volatile("ldmatrix.sync.aligned.m8n8.x4.trans.shared.b16 {%0,%1,%2,%3}, [%4];"
                 : "=r"(r[0]), "=r"(r[1]), "=r"(r[2]), "=r"(r[3]) : "r"(addr));
}
__device__ __forceinline__ void mma_f16(float* c, const unsigned* a, const unsigned* b) {
    asm volatile(
        "mma.sync.aligned.m16n8k16.row.col.f32.f16.f16.f32 "
        "{%0,%1,%2,%3}, {%4,%5,%6,%7}, {%8,%9}, {%0,%1,%2,%3};\n"
        : "+f"(c[0]), "+f"(c[1]), "+f"(c[2]), "+f"(c[3])
        : "r"(a[0]), "r"(a[1]), "r"(a[2]), "r"(a[3]), "r"(b[0]), "r"(b[1]));
}
__device__ __forceinline__ unsigned packh2(float lo, float hi) {
    __half2 h = __halves2half2(__float2half_rn(lo), __float2half_rn(hi));
    return *(unsigned*)&h;
}

// ======================================================================
// Merged prep: RoPE tables | x->half | Wqkv transpose+half | Wout transpose+half
// ======================================================================
#define PREP_ROPE   512
#define PREP_X      16384
#define PREP_WQ     (96 * 64)
#define PREP_WO     (64 * 64)
#define PREP_BLOCKS (PREP_ROPE + PREP_X + PREP_WQ + PREP_WO)

__global__ __launch_bounds__(256) void prep_kernel(
    const float* __restrict__ x, const float* __restrict__ Wqkv, const float* __restrict__ Wout,
    __half* __restrict__ xh, __half* __restrict__ wqh, __half* __restrict__ woh,
    float* __restrict__ ct, float* __restrict__ st)
{
    __shared__ float t[32][33];
    const int bx = blockIdx.x;
    const int tid = threadIdx.x;

    if (bx < PREP_ROPE) {
        int idx = bx * 256 + tid;
        int s = idx >> 6;
        int f = idx & 63;
        double inv = pow(10000.0, -((double)(2 * f)) / 128.0);
        double th = (double)s * inv;
        ct[idx] = (float)cos(th);
        st[idx] = (float)sin(th);
        return;
    }
    if (bx < PREP_ROPE + PREP_X) {
        size_t i = (size_t)(bx - PREP_ROPE) * 256 + tid;
        float4 v = ((const float4*)x)[i];
        ((__half2*)xh)[2 * i]     = __halves2half2(__float2half_rn(v.x), __float2half_rn(v.y));
        ((__half2*)xh)[2 * i + 1] = __halves2half2(__float2half_rn(v.z), __float2half_rn(v.w));
        return;
    }
    const float* src;
    __half* dst;
    int R, C, b;
    if (bx < PREP_ROPE + PREP_X + PREP_WQ) {
        b = bx - (PREP_ROPE + PREP_X);
        src = Wqkv; dst = wqh; R = DIMV; C = QKVW;
        int cb = b % 96, rb = b / 96;
        int c0 = cb * 32, r0 = rb * 32;
        int tx = tid & 31, ty = tid >> 5;
#pragma unroll
        for (int j = 0; j < 4; j++)
            t[ty + j * 8][tx] = src[(size_t)(r0 + ty + j * 8) * C + c0 + tx];
        __syncthreads();
#pragma unroll
        for (int j = 0; j < 4; j++)
            dst[(size_t)(c0 + ty + j * 8) * R + r0 + tx] = __float2half_rn(t[tx][ty + j * 8]);
        return;
    }
    b = bx - (PREP_ROPE + PREP_X + PREP_WQ);
    src = Wout; dst = woh; R = DIMV; C = DIMV;
    {
        int cb = b % 64, rb = b / 64;
        int c0 = cb * 32, r0 = rb * 32;
        int tx = tid & 31, ty = tid >> 5;
#pragma unroll
        for (int j = 0; j < 4; j++)
            t[ty + j * 8][tx] = src[(size_t)(r0 + ty + j * 8) * C + c0 + tx];
        __syncthreads();
#pragma unroll
        for (int j = 0; j < 4; j++)
            dst[(size_t)(c0 + ty + j * 8) * R + r0 + tx] = __float2half_rn(t[tx][ty + j * 8]);
    }
}

// ---------------- GEMM geometry (R8 config): CTA 128x128, 8 warps, warp 64x32 ----------------
#define GBM 128
#define GBN 128
#define GBK 64
#define GA_BYTES (GBM * GBK * 2)           // 16384
#define GB_BYTES (GBN * GBK * 2)           // 16384
#define GSTAGE_BYTES (GA_BYTES + GB_BYTES) // 32768
#define GSMEM_BYTES (3 * GSTAGE_BYTES)     // 98304

#define GEMM_MAINLOOP(Aptr, Bptr, Kdim)                                            \
    auto issue_load = [&](int bufi, int k0) {                                      \
        char* s = smc + bufi * GSTAGE_BYTES;                                       \
        _Pragma("unroll")                                                          \
        for (int rep = 0; rep < 4; rep++) {                                        \
            int idx = tid + rep * 256;                                             \
            int m = idx >> 3, c16 = idx & 7;                                       \
            cp_async16(s + m * 128 + ((c16 ^ (m & 7)) << 4),                       \
                       (Aptr) + (size_t)(row0 + m) * (Kdim) + k0 + c16 * 8);       \
        }                                                                          \
        char* sb = s + GA_BYTES;                                                   \
        _Pragma("unroll")                                                          \
        for (int rep = 0; rep < 4; rep++) {                                        \
            int idx = tid + rep * 256;                                             \
            int n = idx >> 3, c16 = idx & 7;                                       \
            cp_async16(sb + n * 128 + ((c16 ^ (n & 7)) << 4),                      \
                       (Bptr) + (size_t)(col0 + n) * (Kdim) + k0 + c16 * 8);       \
        }                                                                          \
    };                                                                             \
    const int NIT = (Kdim) / GBK;                                                  \
    const int arow_off = ((lane >> 3) & 1) * 8 + (lane & 7);                       \
    const int aseg_hi  = lane >> 4;                                                \
    const int brow_off = ((lane >> 4) & 1) * 8 + (lane & 7);                       \
    const int bseg_hi  = (lane >> 3) & 1;                                          \
    issue_load(0, 0); CP_COMMIT;                                                   \
    issue_load(1, GBK); CP_COMMIT;                                                 \
    int buf = 0, nbuf = 2;                                                         \
    for (int it = 0; it < NIT; it++) {                                             \
        CP_WAIT1;                                                                  \
        __syncthreads();                                                           \
        if (it + 2 < NIT) issue_load(nbuf, (it + 2) * GBK);                        \
        CP_COMMIT;                                                                 \
        const uint32_t sA = sbase + buf * GSTAGE_BYTES;                            \
        const uint32_t sB = sA + GA_BYTES;                                         \
        _Pragma("unroll")                                                          \
        for (int ks = 0; ks < 4; ks++) {                                           \
            unsigned af[4][4], bfr[2][4];                                          \
            _Pragma("unroll")                                                      \
            for (int mt = 0; mt < 4; mt++) {                                       \
                int rrow = wm * 64 + mt * 16 + arow_off;                           \
                int seg = ks * 2 + aseg_hi;                                        \
                ldsm_x4(sA + rrow * 128 + ((seg ^ (rrow & 7)) << 4), af[mt]);      \
            }                                                                      \
            _Pragma("unroll")                                                      \
            for (int p = 0; p < 2; p++) {                                          \
                int rrow = wn * 32 + p * 16 + brow_off;                            \
                int seg = ks * 2 + bseg_hi;                                        \
                ldsm_x4(sB + rrow * 128 + ((seg ^ (rrow & 7)) << 4), bfr[p]);      \
            }                                                                      \
            _Pragma("unroll")                                                      \
            for (int mt = 0; mt < 4; mt++)                                         \
                _Pragma("unroll")                                                  \
                for (int nt = 0; nt < 4; nt++)                                     \
                    mma_f16(acc[mt][nt], af[mt],                                   \
                            (nt & 1) ? &bfr[nt >> 1][2] : &bfr[nt >> 1][0]);       \
        }                                                                          \
        __syncthreads();                                                           \
        buf = (buf == 2) ? 0 : buf + 1;                                            \
        nbuf = (nbuf == 2) ? 0 : nbuf + 1;                                         \
    }

// ======================================================================
// GEMM1 fused (R8): qkvh = rmsnorm+rope( x @ Wqkv ) as fp16.
// ======================================================================
#define XS_STRIDE 132
#define PR_OFF (128 * XS_STRIDE * 4)

__global__ __launch_bounds__(256, 2) void gemm1_fused_kernel(
    const __half* __restrict__ A, const __half* __restrict__ Bt,
    __half* __restrict__ qkvh,
    const float* __restrict__ ct, const float* __restrict__ st)
{
    extern __shared__ char smc[];
    const uint32_t sbase = smem_u32(smc);
    const int tid = threadIdx.x;
    const int warp = tid >> 5;
    const int lane = tid & 31;
    const int grp = lane >> 2;
    const int tig = lane & 3;
    const int wm = warp >> 2;
    const int wn = warp & 3;
    const int row0 = blockIdx.y * GBM;
    const int col0 = blockIdx.x * GBN;

    float acc[4][4][4];
#pragma unroll
    for (int mt = 0; mt < 4; mt++)
#pragma unroll
        for (int nt = 0; nt < 4; nt++)
#pragma unroll
            for (int r = 0; r < 4; r++) acc[mt][nt][r] = 0.f;

    GEMM_MAINLOOP(A, Bt, DIMV)

    if (blockIdx.x >= 20) {
#pragma unroll
        for (int mt = 0; mt < 4; mt++) {
            int row = row0 + wm * 64 + mt * 16 + grp;
#pragma unroll
            for (int nt = 0; nt < 4; nt++) {
                int col = col0 + wn * 32 + nt * 8 + tig * 2;
                *(unsigned*)(qkvh + (size_t)row * QKVW + col) =
                    packh2(acc[mt][nt][0], acc[mt][nt][1]);
                *(unsigned*)(qkvh + (size_t)(row + 8) * QKVW + col) =
                    packh2(acc[mt][nt][2], acc[mt][nt][3]);
            }
        }
        return;
    }

    float* xs = (float*)smc;
    float* pr = (float*)(smc + PR_OFF);

#pragma unroll
    for (int mt = 0; mt < 4; mt++) {
        float s0 = 0.f, s1 = 0.f;
#pragma unroll
        for (int nt = 0; nt < 4; nt++) {
            s0 += acc[mt][nt][0] * acc[mt][nt][0] + acc[mt][nt][1] * acc[mt][nt][1];
            s1 += acc[mt][nt][2] * acc[mt][nt][2] + acc[mt][nt][3] * acc[mt][nt][3];
        }
        s0 += __shfl_xor_sync(0xffffffffu, s0, 1);
        s0 += __shfl_xor_sync(0xffffffffu, s0, 2);
        s1 += __shfl_xor_sync(0xffffffffu, s1, 1);
        s1 += __shfl_xor_sync(0xffffffffu, s1, 2);
        if (tig == 0) {
            pr[(wm * 64 + mt * 16 + grp) * 4 + wn]     = s0;
            pr[(wm * 64 + mt * 16 + grp + 8) * 4 + wn] = s1;
        }
    }
    __syncthreads();

#pragma unroll
    for (int mt = 0; mt < 4; mt++) {
        int r0l = wm * 64 + mt * 16 + grp;
        int r1l = r0l + 8;
        float sc0 = rsqrtf((pr[r0l * 4] + pr[r0l * 4 + 1] + pr[r0l * 4 + 2] + pr[r0l * 4 + 3])
                           * (1.0f / 128.0f) + RMS_EPS);
        float sc1 = rsqrtf((pr[r1l * 4] + pr[r1l * 4 + 1] + pr[r1l * 4 + 2] + pr[r1l * 4 + 3])
                           * (1.0f / 128.0f) + RMS_EPS);
#pragma unroll
        for (int nt = 0; nt < 4; nt++) {
            int col = wn * 32 + nt * 8 + tig * 2;
            xs[r0l * XS_STRIDE + col]     = acc[mt][nt][0] * sc0;
            xs[r0l * XS_STRIDE + col + 1] = acc[mt][nt][1] * sc0;
            xs[r1l * XS_STRIDE + col]     = acc[mt][nt][2] * sc1;
            xs[r1l * XS_STRIDE + col + 1] = acc[mt][nt][3] * sc1;
        }
    }
    __syncthreads();

    const float2* ctp = (const float2*)ct;
    const float2* stp = (const float2*)st;
#pragma unroll 2
    for (int rr = 0; rr < 16; rr++) {
        int row = warp * 16 + rr;
        int s = (row0 + row) & (SEQ - 1);
        float2 xa = *(const float2*)&xs[row * XS_STRIDE + 2 * lane];
        float2 xb = *(const float2*)&xs[row * XS_STRIDE + 64 + 2 * lane];
        float2 c = ctp[s * 32 + lane];
        float2 sn = stp[s * 32 + lane];
        unsigned lo = packh2(xa.x * c.x + xb.x * sn.x, xa.y * c.y + xb.y * sn.y);
        unsigned hi = packh2(xb.x * c.x - xa.x * sn.x, xb.y * c.y - xa.y * sn.y);
        size_t gb = (size_t)(row0 + row) * QKVW + col0 + 2 * lane;
        *(unsigned*)(qkvh + gb)      = lo;
        *(unsigned*)(qkvh + gb + 64) = hi;
    }
}

// ======================================================================
// GEMM2 (R8): out[M,N] fp32 = A[M,K] @ Bt[N,K]^T
// ======================================================================
__global__ __launch_bounds__(256, 2) void gemm_f16_kernel(
    const __half* __restrict__ A, const __half* __restrict__ Bt, float* __restrict__ C,
    int M, int N, int K)
{
    extern __shared__ char smc[];
    const uint32_t sbase = smem_u32(smc);
    const int tid = threadIdx.x;
    const int warp = tid >> 5;
    const int lane = tid & 31;
    const int grp = lane >> 2;
    const int tig = lane & 3;
    const int wm = warp >> 2;
    const int wn = warp & 3;
    const int row0 = blockIdx.y * GBM;
    const int col0 = blockIdx.x * GBN;

    float acc[4][4][4];
#pragma unroll
    for (int mt = 0; mt < 4; mt++)
#pragma unroll
        for (int nt = 0; nt < 4; nt++)
#pragma unroll
            for (int r = 0; r < 4; r++) acc[mt][nt][r] = 0.f;

    GEMM_MAINLOOP(A, Bt, K)

#pragma unroll
    for (int mt = 0; mt < 4; mt++) {
        int row = row0 + wm * 64 + mt * 16 + grp;
#pragma unroll
        for (int nt = 0; nt < 4; nt++) {
            int col = col0 + wn * 32 + nt * 8 + tig * 2;
            *(float2*)(C + (size_t)row * N + col) =
                make_float2(acc[mt][nt][0], acc[mt][nt][1]);
            *(float2*)(C + (size_t)(row + 8) * N + col) =
                make_float2(acc[mt][nt][2], acc[mt][nt][3]);
        }
    }
}

// ======================================================================
// FP16 flash attention: BM=64 Q rows, 4 warps (128 thr), 2 CTAs/SM.
// Per-warp layout identical to R8 (16 rows/warp); KV double-buffered.
// smem: 2 stages x (K 16KB + V 16KB) = 64KB; Q staging (16KB) aliases stage 0.
// ======================================================================
#define AT_SMEM_BYTES 65536

__global__ __launch_bounds__(128, 2) void attn_f16_kernel(
    const __half* __restrict__ qkvh, __half* __restrict__ yh)
{
    extern __shared__ char smc[];
    const uint32_t sbase = smem_u32(smc);
    const int tid = threadIdx.x;
    const int warp = tid >> 5;
    const int lane = tid & 31;
    const int grp = lane >> 2;
    const int tig = lane & 3;

    const int i0 = (gridDim.x - 1 - blockIdx.x) * 64;   // heavy tiles first
    const int bh = blockIdx.y;
    const int b = bh >> 4;
    const int h = bh & 15;
    const int kvh = h >> 2;

    const size_t rowb = (size_t)b * SEQ * QKVW;
    const int qcol = h * HD;
    const int kcol = DIMV + kvh * HD;
    const int vcol = DIMV + NKV * HD + kvh * HD;

    // ---- stage Q (64 rows x 256B) into stage-0 region, swizzled ----
#pragma unroll
    for (int rep = 0; rep < 8; rep++) {
        int idx = tid + rep * 128;            // 0..1023
        int row = idx >> 4, seg = idx & 15;
        cp_async16(smc + row * 256 + ((seg ^ (row & 7)) << 4),
                   qkvh + rowb + (size_t)(i0 + row) * QKVW + qcol + seg * 8);
    }
    CP_COMMIT; CP_WAIT0;
    __syncthreads();

    const int arow_off = ((lane >> 3) & 1) * 8 + (lane & 7);
    const int aseg_hi  = lane >> 4;
    unsigned qf[8][4];
    {
        int row = warp * 16 + arow_off;
#pragma unroll
        for (int ks = 0; ks < 8; ks++) {
            int seg = ks * 2 + aseg_hi;
            ldsm_x4(sbase + row * 256 + ((seg ^ (row & 7)) << 4), qf[ks]);
        }
    }
    __syncthreads();   // Q reads done; KV buffers may overwrite

    auto issue_kv = [&](int buf, int j0) {
        char* Ks = smc + buf * 32768;
        char* Vs = Ks + 16384;
#pragma unroll
        for (int rep = 0; rep < 8; rep++) {
            int idx = tid + rep * 128;        // 0..1023
            int row = idx >> 4, seg = idx & 15;
            const __half* kr = qkvh + rowb + (size_t)(j0 + row) * QKVW;
            uint32_t d = row * 256 + ((seg ^ (row & 7)) << 4);
            cp_async16(Ks + d, kr + kcol + seg * 8);
            cp_async16(Vs + d, kr + vcol + seg * 8);
        }
    };

    float of[16][4];
#pragma unroll
    for (int nf = 0; nf < 16; nf++)
#pragma unroll
        for (int r = 0; r < 4; r++) of[nf][r] = 0.f;
    float m0 = -CUDART_INF_F, m1 = -CUDART_INF_F, l0 = 0.f, l1 = 0.f;

    const int qi0 = i0 + warp * 16 + grp;
    const int qi1 = qi0 + 8;
    const int NIT = (i0 + 64) / 64;

    const int brow_off = ((lane >> 4) & 1) * 8 + (lane & 7);
    const int bseg_hi  = (lane >> 3) & 1;
    const int vrow_off = ((lane >> 3) & 1) * 8 + (lane & 7);
    const int vseg_hi  = (lane >> 4) & 1;

    issue_kv(0, 0); CP_COMMIT;

    for (int it = 0; it < NIT; it++) {
        const int j0 = it * 64;
        const int buf = it & 1;
        if (it + 1 < NIT) issue_kv(buf ^ 1, j0 + 64);
        CP_COMMIT;
        CP_WAIT1;
        __syncthreads();

        const uint32_t Kb = sbase + buf * 32768;
        const uint32_t Vb = Kb + 16384;

        // ---- S = Q K^T ----
        float sacc[8][4];
#pragma unroll
        for (int nf = 0; nf < 8; nf++)
#pragma unroll
            for (int r = 0; r < 4; r++) sacc[nf][r] = 0.f;

#pragma unroll
        for (int ks = 0; ks < 8; ks++) {
            unsigned bf[4][4];
#pragma unroll
            for (int p = 0; p < 4; p++) {
                int row = p * 16 + brow_off;
                int seg = ks * 2 + bseg_hi;
                ldsm_x4(Kb + row * 256 + ((seg ^ (row & 7)) << 4), bf[p]);
            }
#pragma unroll
            for (int nf = 0; nf < 8; nf++)
                mma_f16(sacc[nf], qf[ks], (nf & 1) ? &bf[nf >> 1][2] : &bf[nf >> 1][0]);
        }

        // ---- causal mask (diagonal tile only: j0 == i0) ----
        if (j0 + 63 > i0 + warp * 16 + 15 || j0 + 63 > qi0 || j0 + 63 > qi1) {
            // cheap uniform test: only final tile can mask (j0 == i0)
        }
        if (it == NIT - 1) {
#pragma unroll
            for (int nf = 0; nf < 8; nf++) {
                int key = j0 + nf * 8 + 2 * tig;
                if (key     > qi0) sacc[nf][0] = -CUDART_INF_F;
                if (key + 1 > qi0) sacc[nf][1] = -CUDART_INF_F;
                if (key     > qi1) sacc[nf][2] = -CUDART_INF_F;
                if (key + 1 > qi1) sacc[nf][3] = -CUDART_INF_F;
            }
        }

        // ---- online softmax ----
        float mx0 = -CUDART_INF_F, mx1 = -CUDART_INF_F;
#pragma unroll
        for (int nf = 0; nf < 8; nf++) {
            mx0 = fmaxf(mx0, fmaxf(sacc[nf][0], sacc[nf][1]));
            mx1 = fmaxf(mx1, fmaxf(sacc[nf][2], sacc[nf][3]));
        }
        mx0 = fmaxf(mx0, __shfl_xor_sync(0xffffffffu, mx0, 1));
        mx0 = fmaxf(mx0, __shfl_xor_sync(0xffffffffu, mx0, 2));
        mx1 = fmaxf(mx1, __shfl_xor_sync(0xffffffffu, mx1, 1));
        mx1 = fmaxf(mx1, __shfl_xor_sync(0xffffffffu, mx1, 2));

        float m0n = fmaxf(m0, mx0);
        float m1n = fmaxf(m1, mx1);
        float alpha0 = __expf((m0 - m0n) * ATT_SCALE);
        float alpha1 = __expf((m1 - m1n) * ATT_SCALE);
        m0 = m0n; m1 = m1n;

        unsigned ph[8][2];
        float rs0 = 0.f, rs1 = 0.f;
#pragma unroll
        for (int nf = 0; nf < 8; nf++) {
            float p0 = __expf((sacc[nf][0] - m0) * ATT_SCALE);
            float p1 = __expf((sacc[nf][1] - m0) * ATT_SCALE);
            float p2 = __expf((sacc[nf][2] - m1) * ATT_SCALE);
            float p3 = __expf((sacc[nf][3] - m1) * ATT_SCALE);
            rs0 += p0 + p1;
            rs1 += p2 + p3;
            ph[nf][0] = packh2(p0, p1);
            ph[nf][1] = packh2(p2, p3);
        }
        rs0 += __shfl_xor_sync(0xffffffffu, rs0, 1);
        rs0 += __shfl_xor_sync(0xffffffffu, rs0, 2);
        rs1 += __shfl_xor_sync(0xffffffffu, rs1, 1);
        rs1 += __shfl_xor_sync(0xffffffffu, rs1, 2);
        l0 = l0 * alpha0 + rs0;
        l1 = l1 * alpha1 + rs1;

#pragma unroll
        for (int nf = 0; nf < 16; nf++) {
            of[nf][0] *= alpha0; of[nf][1] *= alpha0;
            of[nf][2] *= alpha1; of[nf][3] *= alpha1;
        }

        // ---- O += P V ----
#pragma unroll
        for (int ks = 0; ks < 4; ks++) {
            unsigned af[4] = {ph[2 * ks][0], ph[2 * ks][1],
                              ph[2 * ks + 1][0], ph[2 * ks + 1][1]};
#pragma unroll
            for (int p = 0; p < 8; p++) {
                int row = ks * 16 + vrow_off;
                int seg = p * 2 + vseg_hi;
                unsigned vf[4];
                ldsm_x4_t(Vb + row * 256 + ((seg ^ (row & 7)) << 4), vf);
                mma_f16(of[2 * p],     af, &vf[0]);
                mma_f16(of[2 * p + 1], af, &vf[2]);
            }
        }
        __syncthreads();
    }

    float inv0 = 1.0f / l0, inv1 = 1.0f / l1;
    int r0 = i0 + warp * 16 + grp;
    __half* dst0 = yh + (size_t)(b * SEQ + r0) * DIMV + h * HD;
    __half* dst1 = yh + (size_t)(b * SEQ + r0 + 8) * DIMV + h * HD;
#pragma unroll
    for (int nf = 0; nf < 16; nf++) {
        *(unsigned*)(dst0 + nf * 8 + 2 * tig) = packh2(of[nf][0] * inv0, of[nf][1] * inv0);
        *(unsigned*)(dst1 + nf * 8 + 2 * tig) = packh2(of[nf][2] * inv1, of[nf][3] * inv1);
    }
}

// ================= launch =================
extern "C" void kernel_launch(void* const* d_in, const int* in_sizes, int n_in,
                              void* d_out, int out_size)
{
    const float* x    = (const float*)d_in[0];
    const float* Wqkv = (const float*)d_in[1];
    const float* Wout = (const float*)d_in[2];
    float* out = (float*)d_out;

    float *ct, *st;
    __half *qkvh, *yh, *xh, *wqh, *woh;
    cudaGetSymbolAddress((void**)&qkvh, g_qkvh);
    cudaGetSymbolAddress((void**)&yh,   g_yh);
    cudaGetSymbolAddress((void**)&xh,   g_xh);
    cudaGetSymbolAddress((void**)&wqh,  g_wqh);
    cudaGetSymbolAddress((void**)&woh,  g_woh);
    cudaGetSymbolAddress((void**)&ct,   g_cos);
    cudaGetSymbolAddress((void**)&st,   g_sin);

    // 1. merged prep
    prep_kernel<<<PREP_BLOCKS, 256>>>(x, Wqkv, Wout, xh, wqh, woh, ct, st);

    // 2. QKV projection fused with RMS-norm + RoPE -> fp16 qkv
    cudaFuncSetAttribute(gemm1_fused_kernel, cudaFuncAttributeMaxDynamicSharedMemorySize, GSMEM_BYTES);
    gemm1_fused_kernel<<<dim3(QKVW / GBN, NTOK / GBM), 256, GSMEM_BYTES>>>(
        xh, wqh, qkvh, ct, st);

    // 3. causal GQA flash attention (BM=64, 2 CTAs/SM)
    cudaFuncSetAttribute(attn_f16_kernel, cudaFuncAttributeMaxDynamicSharedMemorySize, AT_SMEM_BYTES);
    attn_f16_kernel<<<dim3(SEQ / 64, BATCH * NHEAD), 128, AT_SMEM_BYTES>>>(qkvh, yh);

    // 4. output projection
    cudaFuncSetAttribute(gemm_f16_kernel, cudaFuncAttributeMaxDynamicSharedMemorySize, GSMEM_BYTES);
    gemm_f16_kernel<<<dim3(DIMV / GBN, NTOK / GBM), 256, GSMEM_BYTES>>>(
        yh, woh, out, NTOK, DIMV, DIMV);
}